// round 1
// baseline (speedup 1.0000x reference)
#include <cuda_runtime.h>
#include <cstdint>

// Problem constants
#define N_NODES 50000
#define E_EDGES 300000
#define IN_F    128
#define HFEAT   64
#define AHEADS  4
#define R_REL   3
#define H_DIM   256
#define RH      768          // R_REL * H_DIM
#define RN      (R_REL * N_NODES)
#define RE      (R_REL * E_EDGES)

// ---------------- device scratch (static, no allocations) ----------------
__device__ float g_hw [(size_t)N_NODES * RH];   // h @ [wW0|wW1|wW2] + bias  (153.6 MB)
__device__ float g_agg[(size_t)N_NODES * RH];   // concat of per-relation aggregates (153.6 MB)
__device__ float g_sa[N_NODES];                 // a_n = h.(dW u)  (+ const folded later)
__device__ float g_sb[N_NODES];                 // b_n = h.(dW v)
__device__ float g_pq[(size_t)RN * 8];          // per (r,node): p[0..3], q[0..3] (q incl qc+ab)
__device__ float g_du[IN_F];
__device__ float g_dv[IN_F];
__device__ float g_PQ[R_REL * IN_F * 8];        // [r][i][8]: P heads 0..3, Q heads 0..3
__device__ float g_pqc[R_REL * 8];              // bias constants for p (0..3) and q (4..7)
__device__ float g_Cs;                          // db.(u+v) + fb
__device__ int   g_cnt[RN];
__device__ int   g_off[RN + 1];
__device__ int   g_cur[RN];
__device__ int   g_elist[RE];

// ---------------- kernel 1: tiny precompute of folded parameters ----------------
__global__ void k_precompute(const float* __restrict__ dW, const float* __restrict__ db,
                             const float* __restrict__ fW, const float* __restrict__ fb,
                             const float* __restrict__ wW, const float* __restrict__ wb,
                             const float* __restrict__ aW, const float* __restrict__ ab)
{
    int i = threadIdx.x;            // 0..127
    if (i < IN_F) {
        float s1 = 0.f, s2 = 0.f;
        for (int j = 0; j < H_DIM; j++) {
            float u = fW[j] + fW[512 + j];
            float v = fW[256 + j] - fW[512 + j];
            float w = dW[i * H_DIM + j];
            s1 = fmaf(w, u, s1);
            s2 = fmaf(w, v, s2);
        }
        g_du[i] = s1;
        g_dv[i] = s2;
        for (int r = 0; r < R_REL; r++) {
            for (int hd = 0; hd < AHEADS; hd++) {
                float p = 0.f, q = 0.f;
                const float* wr = wW + (size_t)r * IN_F * H_DIM + (size_t)i * H_DIM + hd * HFEAT;
                const float* a1 = aW + r * 2 * HFEAT;
                const float* a2 = a1 + HFEAT;
                for (int k = 0; k < HFEAT; k++) {
                    p = fmaf(wr[k], a1[k], p);
                    q = fmaf(wr[k], a2[k], q);
                }
                g_PQ[r * (IN_F * 8) + i * 8 + hd]     = p;
                g_PQ[r * (IN_F * 8) + i * 8 + 4 + hd] = q;
            }
        }
    }
    if (i == 0) {
        float cs = fb[0];
        for (int j = 0; j < H_DIM; j++) {
            float u = fW[j] + fW[512 + j];
            float v = fW[256 + j] - fW[512 + j];
            cs = fmaf(db[j], u + v, cs);
        }
        g_Cs = cs;
        for (int r = 0; r < R_REL; r++) {
            for (int hd = 0; hd < AHEADS; hd++) {
                float pc = 0.f, qc = 0.f;
                const float* wr = wb + r * H_DIM + hd * HFEAT;
                const float* a1 = aW + r * 2 * HFEAT;
                const float* a2 = a1 + HFEAT;
                for (int k = 0; k < HFEAT; k++) {
                    pc = fmaf(wr[k], a1[k], pc);
                    qc = fmaf(wr[k], a2[k], qc);
                }
                g_pqc[r * 8 + hd]     = pc;
                g_pqc[r * 8 + 4 + hd] = qc + ab[r];
            }
        }
    }
}

// ---------------- kernel 2: per-node scalars (warp per node) ----------------
__global__ __launch_bounds__(128) void k_node_scalars(const float* __restrict__ h)
{
    int warp = threadIdx.x >> 5;
    int lane = threadIdx.x & 31;
    int node = blockIdx.x * 4 + warp;
    if (node >= N_NODES) return;

    float4 h4 = *(const float4*)(h + (size_t)node * IN_F + lane * 4);
    const float* hv = (const float*)&h4;

    float a = 0.f, b = 0.f;
    float pr[24];
#pragma unroll
    for (int j = 0; j < 24; j++) pr[j] = 0.f;

#pragma unroll
    for (int t = 0; t < 4; t++) {
        float x = hv[t];
        int idx = lane * 4 + t;
        a = fmaf(x, g_du[idx], a);
        b = fmaf(x, g_dv[idx], b);
#pragma unroll
        for (int r = 0; r < R_REL; r++) {
            const float4* pq4 = (const float4*)&g_PQ[r * (IN_F * 8) + idx * 8];
            float4 c0 = pq4[0], c1 = pq4[1];
            const float* c = (const float*)&c0;
            const float* d = (const float*)&c1;
#pragma unroll
            for (int j = 0; j < 4; j++) {
                pr[r * 8 + j]     = fmaf(x, c[j], pr[r * 8 + j]);
                pr[r * 8 + 4 + j] = fmaf(x, d[j], pr[r * 8 + 4 + j]);
            }
        }
    }
#pragma unroll
    for (int off = 16; off; off >>= 1) {
        a += __shfl_xor_sync(0xffffffffu, a, off);
        b += __shfl_xor_sync(0xffffffffu, b, off);
#pragma unroll
        for (int j = 0; j < 24; j++)
            pr[j] += __shfl_xor_sync(0xffffffffu, pr[j], off);
    }
    if (lane == 0) {
        g_sa[node] = a;
        g_sb[node] = b;
#pragma unroll
        for (int r = 0; r < R_REL; r++)
#pragma unroll
            for (int j = 0; j < 8; j++)
                g_pq[((size_t)r * N_NODES + node) * 8 + j] = pr[r * 8 + j] + g_pqc[r * 8 + j];
    }
}

// ---------------- GEMM: C[M,Ncols] = A[M,K] @ B + bias ----------------
// splitB=1: B is wW laid out [R][K][256] and column blocks of 128 never straddle relations.
#define BM 128
#define BN 128
#define BK 16
__global__ __launch_bounds__(256) void k_gemm(const float* __restrict__ A,
                                              const float* __restrict__ B,
                                              const float* __restrict__ bias,
                                              float* __restrict__ C,
                                              int M, int Ncols, int K, int splitB)
{
    __shared__ float As[BK][BM];
    __shared__ float Bs[BK][BN];

    int tid = threadIdx.x;
    int bx = blockIdx.x, by = blockIdx.y;
    int tx = tid & 15, ty = tid >> 4;

    const float* Bp;
    int bn0, ldB;
    if (splitB) {
        int rblk = (bx * BN) / 256;
        Bp = B + (size_t)rblk * K * 256;
        bn0 = bx * BN - rblk * 256;
        ldB = 256;
    } else {
        Bp = B; bn0 = bx * BN; ldB = Ncols;
    }

    int arow0 = by * BM;
    float acc[8][8];
#pragma unroll
    for (int i = 0; i < 8; i++)
#pragma unroll
        for (int j = 0; j < 8; j++) acc[i][j] = 0.f;

    for (int kk = 0; kk < K; kk += BK) {
#pragma unroll
        for (int it = 0; it < 2; it++) {
            int lin = tid + it * 256;
            int row = lin >> 2, c4 = lin & 3;
            int gm = arow0 + row;
            float4 v = make_float4(0.f, 0.f, 0.f, 0.f);
            if (gm < M) v = *(const float4*)(A + (size_t)gm * K + kk + c4 * 4);
            As[c4 * 4 + 0][row] = v.x;
            As[c4 * 4 + 1][row] = v.y;
            As[c4 * 4 + 2][row] = v.z;
            As[c4 * 4 + 3][row] = v.w;
        }
#pragma unroll
        for (int it = 0; it < 2; it++) {
            int lin = tid + it * 256;
            int brow = lin >> 5, bc = (lin & 31) * 4;
            float4 v = *(const float4*)(Bp + (size_t)(kk + brow) * ldB + bn0 + bc);
            *(float4*)&Bs[brow][bc] = v;
        }
        __syncthreads();
#pragma unroll
        for (int k = 0; k < BK; k++) {
            float4 a0 = *(const float4*)&As[k][ty * 8];
            float4 a1 = *(const float4*)&As[k][ty * 8 + 4];
            float4 b0 = *(const float4*)&Bs[k][tx * 8];
            float4 b1 = *(const float4*)&Bs[k][tx * 8 + 4];
            float av[8] = {a0.x, a0.y, a0.z, a0.w, a1.x, a1.y, a1.z, a1.w};
            float bv[8] = {b0.x, b0.y, b0.z, b0.w, b1.x, b1.y, b1.z, b1.w};
#pragma unroll
            for (int i = 0; i < 8; i++)
#pragma unroll
                for (int j = 0; j < 8; j++)
                    acc[i][j] = fmaf(av[i], bv[j], acc[i][j]);
        }
        __syncthreads();
    }

    int col0 = bx * BN + tx * 8;
    float4 bs0 = *(const float4*)&bias[col0];
    float4 bs1 = *(const float4*)&bias[col0 + 4];
    const float* bb0 = (const float*)&bs0;
    const float* bb1 = (const float*)&bs1;
#pragma unroll
    for (int i = 0; i < 8; i++) {
        int gm = arow0 + ty * 8 + i;
        if (gm < M) {
            float4 o0 = make_float4(acc[i][0] + bb0[0], acc[i][1] + bb0[1],
                                    acc[i][2] + bb0[2], acc[i][3] + bb0[3]);
            float4 o1 = make_float4(acc[i][4] + bb1[0], acc[i][5] + bb1[1],
                                    acc[i][6] + bb1[2], acc[i][7] + bb1[3]);
            *(float4*)(C + (size_t)gm * Ncols + col0)     = o0;
            *(float4*)(C + (size_t)gm * Ncols + col0 + 4) = o1;
        }
    }
}

// ---------------- CSR build ----------------
__global__ void k_zero()
{
    int i = blockIdx.x * blockDim.x + threadIdx.x;
    if (i < RN) g_cnt[i] = 0;
}

__global__ void k_hist(const int* __restrict__ dst)
{
    int i = blockIdx.x * blockDim.x + threadIdx.x;
    if (i < RE) {
        int r = i / E_EDGES;
        atomicAdd(&g_cnt[r * N_NODES + dst[i]], 1);
    }
}

__global__ __launch_bounds__(1024) void k_scan()
{
    __shared__ int sm[1024];
    int tid = threadIdx.x;
    int carry = 0;
    for (int base = 0; base < RN; base += 1024) {
        int i = base + tid;
        int v = (i < RN) ? g_cnt[i] : 0;
        sm[tid] = v;
        __syncthreads();
#pragma unroll
        for (int off = 1; off < 1024; off <<= 1) {
            int t = (tid >= off) ? sm[tid - off] : 0;
            __syncthreads();
            sm[tid] += t;
            __syncthreads();
        }
        int excl = carry + sm[tid] - v;
        if (i < RN) { g_off[i] = excl; g_cur[i] = excl; }
        carry += sm[1023];
        __syncthreads();
    }
    if (tid == 0) g_off[RN] = carry;
}

__global__ void k_scatter(const int* __restrict__ dst)
{
    int i = blockIdx.x * blockDim.x + threadIdx.x;
    if (i < RE) {
        int r = i / E_EDGES;
        int pos = atomicAdd(&g_cur[r * N_NODES + dst[i]], 1);
        g_elist[pos] = i - r * E_EDGES;
    }
}

// ---------------- aggregation: warp per (relation, node), online softmax ----------------
__global__ __launch_bounds__(256) void k_agg(const int* __restrict__ src)
{
    int widx = (blockIdx.x * blockDim.x + threadIdx.x) >> 5;
    int lane = threadIdx.x & 31;
    if (widx >= RN) return;
    int r = widx / N_NODES;
    int n = widx - r * N_NODES;
    int start = g_off[widx], end = g_off[widx + 1];
    size_t obase = (size_t)n * RH + r * H_DIM;

    if (start == end) {
#pragma unroll
        for (int k = 0; k < 8; k++) g_agg[obase + lane + 32 * k] = 0.f;
        return;
    }

    float qv[4];
    {
        const float* qp = &g_pq[((size_t)r * N_NODES + n) * 8 + 4];
#pragma unroll
        for (int hh = 0; hh < 4; hh++) qv[hh] = qp[hh];
    }
    float b_n = g_sb[n];
    float cs = g_Cs;
    const float* hwbase = g_hw + r * H_DIM;
    const int* srcR = src + (size_t)r * E_EDGES;

    float m[4], den[4], acc[8];
#pragma unroll
    for (int hh = 0; hh < 4; hh++) { m[hh] = -1e30f; den[hh] = 0.f; }
#pragma unroll
    for (int k = 0; k < 8; k++) acc[k] = 0.f;

    for (int pos = start; pos < end; pos++) {
        int e = g_elist[pos];
        int s = srcR[e];
        float sc = g_sa[s] + b_n + cs;
        float sgn = (float)((sc > 0.f) - (sc < 0.f));
        float4 pv = *(const float4*)&g_pq[((size_t)r * N_NODES + s) * 8];
        float pvv[4] = {pv.x, pv.y, pv.z, pv.w};
        float f[4], w[4];
#pragma unroll
        for (int hh = 0; hh < 4; hh++) {
            float al = fmaf(sgn, pvv[hh], qv[hh]);
            al = (al > 0.f) ? al : 0.01f * al;
            float nm = fmaxf(m[hh], al);
            f[hh] = __expf(m[hh] - nm);
            float wv = __expf(al - nm);
            den[hh] = den[hh] * f[hh] + wv;
            m[hh] = nm;
            w[hh] = wv * sgn;
        }
        const float* row = hwbase + (size_t)s * RH;
#pragma unroll
        for (int k = 0; k < 8; k++)
            acc[k] = fmaf(acc[k], f[k >> 1], 0.f) + w[k >> 1] * row[lane + 32 * k];
    }
    float inv[4];
#pragma unroll
    for (int hh = 0; hh < 4; hh++) inv[hh] = 1.f / den[hh];
#pragma unroll
    for (int k = 0; k < 8; k++)
        g_agg[obase + lane + 32 * k] = acc[k] * inv[k >> 1];
}

// ---------------- launch ----------------
extern "C" void kernel_launch(void* const* d_in, const int* in_sizes, int n_in,
                              void* d_out, int out_size)
{
    const float* h    = (const float*)d_in[0];
    const float* dW   = (const float*)d_in[1];
    const float* db   = (const float*)d_in[2];
    const float* fW   = (const float*)d_in[3];
    const float* fb   = (const float*)d_in[4];
    const float* wW   = (const float*)d_in[5];
    const float* wb   = (const float*)d_in[6];
    const float* aW   = (const float*)d_in[7];
    const float* ab   = (const float*)d_in[8];
    const float* linW = (const float*)d_in[9];
    const float* linb = (const float*)d_in[10];
    const int*   src  = (const int*)d_in[11];
    const int*   dst  = (const int*)d_in[12];
    float* out = (float*)d_out;

    float *p_hw = nullptr, *p_agg = nullptr;
    cudaGetSymbolAddress((void**)&p_hw, g_hw);
    cudaGetSymbolAddress((void**)&p_agg, g_agg);

    k_precompute<<<1, 128>>>(dW, db, fW, fb, wW, wb, aW, ab);
    k_node_scalars<<<N_NODES / 4, 128>>>(h);
    k_gemm<<<dim3(RH / BN, (N_NODES + BM - 1) / BM), 256>>>(h, wW, wb, p_hw,
                                                            N_NODES, RH, IN_F, 1);
    k_zero<<<(RN + 255) / 256, 256>>>();
    k_hist<<<(RE + 255) / 256, 256>>>(dst);
    k_scan<<<1, 1024>>>();
    k_scatter<<<(RE + 255) / 256, 256>>>(dst);
    k_agg<<<RN / 8, 256>>>(src);
    k_gemm<<<dim3(H_DIM / BN, (N_NODES + BM - 1) / BM), 256>>>(p_agg, linW, linb, out,
                                                               N_NODES, H_DIM, RH, 0);
}

// round 4
// speedup vs baseline: 1.0187x; 1.0187x over previous
#include <cuda_runtime.h>
#include <cstdint>

// Problem constants
#define N_NODES 50000
#define E_EDGES 300000
#define IN_F    128
#define HFEAT   64
#define AHEADS  4
#define R_REL   3
#define H_DIM   256
#define RH      768          // R_REL * H_DIM
#define RN      (R_REL * N_NODES)
#define RE      (R_REL * E_EDGES)

// ---------------- device scratch (static, no allocations) ----------------
__device__ float g_hw [(size_t)N_NODES * RH];   // h @ [wW0|wW1|wW2] + bias  (153.6 MB)
__device__ float g_agg[(size_t)N_NODES * RH];   // concat of per-relation aggregates (153.6 MB)
__device__ float g_sa[N_NODES];                 // a_n = h.(dW u)
__device__ float g_sb[N_NODES];                 // b_n = h.(dW v)
__device__ float g_pq[(size_t)RN * 8];          // per (r,node): p[0..3], q[0..3] (q incl qc+ab)
__device__ float g_du[IN_F];
__device__ float g_dv[IN_F];
__device__ float g_PQ[R_REL * IN_F * 8];        // [r][i][8]: P heads 0..3, Q heads 0..3
__device__ float g_pqc[R_REL * 8];              // bias constants for p (0..3) and q (4..7)
__device__ float g_Cs;                          // db.(u+v) + fb
__device__ int   g_cnt[RN];
__device__ int   g_off[RN + 1];
__device__ int   g_cur[RN];
__device__ int   g_elist[RE];

// ---------------- f32x2 helpers ----------------
__device__ __forceinline__ uint64_t pk2(float lo, float hi)
{
    uint64_t r;
    asm("mov.b64 %0, {%1, %2};" : "=l"(r) : "f"(lo), "f"(hi));
    return r;
}
__device__ __forceinline__ void unpk2(float& lo, float& hi, uint64_t v)
{
    asm("mov.b64 {%0, %1}, %2;" : "=f"(lo), "=f"(hi) : "l"(v));
}
__device__ __forceinline__ void ffma2(uint64_t& d, uint64_t a, uint64_t b)
{
    asm("fma.rn.f32x2 %0, %1, %2, %0;" : "+l"(d) : "l"(a), "l"(b));
}

// ---------------- kernel: tiny precompute of folded sign/attention params ----------------
__global__ void k_precompute(const float* __restrict__ dW, const float* __restrict__ db,
                             const float* __restrict__ fW, const float* __restrict__ fb,
                             const float* __restrict__ wW, const float* __restrict__ wb,
                             const float* __restrict__ aW, const float* __restrict__ ab)
{
    int i = threadIdx.x;            // 0..127
    if (i < IN_F) {
        float s1 = 0.f, s2 = 0.f;
        for (int j = 0; j < H_DIM; j++) {
            float u = fW[j] + fW[512 + j];
            float v = fW[256 + j] - fW[512 + j];
            float w = dW[i * H_DIM + j];
            s1 = fmaf(w, u, s1);
            s2 = fmaf(w, v, s2);
        }
        g_du[i] = s1;
        g_dv[i] = s2;
        for (int r = 0; r < R_REL; r++) {
            for (int hd = 0; hd < AHEADS; hd++) {
                float p = 0.f, q = 0.f;
                const float* wr = wW + (size_t)r * IN_F * H_DIM + (size_t)i * H_DIM + hd * HFEAT;
                const float* a1 = aW + r * 2 * HFEAT;
                const float* a2 = a1 + HFEAT;
                for (int k = 0; k < HFEAT; k++) {
                    p = fmaf(wr[k], a1[k], p);
                    q = fmaf(wr[k], a2[k], q);
                }
                g_PQ[r * (IN_F * 8) + i * 8 + hd]     = p;
                g_PQ[r * (IN_F * 8) + i * 8 + 4 + hd] = q;
            }
        }
    }
    if (i == 0) {
        float cs = fb[0];
        for (int j = 0; j < H_DIM; j++) {
            float u = fW[j] + fW[512 + j];
            float v = fW[256 + j] - fW[512 + j];
            cs = fmaf(db[j], u + v, cs);
        }
        g_Cs = cs;
        for (int r = 0; r < R_REL; r++) {
            for (int hd = 0; hd < AHEADS; hd++) {
                float pc = 0.f, qc = 0.f;
                const float* wr = wb + r * H_DIM + hd * HFEAT;
                const float* a1 = aW + r * 2 * HFEAT;
                const float* a2 = a1 + HFEAT;
                for (int k = 0; k < HFEAT; k++) {
                    pc = fmaf(wr[k], a1[k], pc);
                    qc = fmaf(wr[k], a2[k], qc);
                }
                g_pqc[r * 8 + hd]     = pc;
                g_pqc[r * 8 + 4 + hd] = qc + ab[r];
            }
        }
    }
}

// ---------------- kernel: per-node scalars (warp per node) ----------------
__global__ __launch_bounds__(128) void k_node_scalars(const float* __restrict__ h)
{
    int warp = threadIdx.x >> 5;
    int lane = threadIdx.x & 31;
    int node = blockIdx.x * 4 + warp;
    if (node >= N_NODES) return;

    float4 h4 = *(const float4*)(h + (size_t)node * IN_F + lane * 4);
    const float* hv = (const float*)&h4;

    float a = 0.f, b = 0.f;
    float pr[24];
#pragma unroll
    for (int j = 0; j < 24; j++) pr[j] = 0.f;

#pragma unroll
    for (int t = 0; t < 4; t++) {
        float x = hv[t];
        int idx = lane * 4 + t;
        a = fmaf(x, g_du[idx], a);
        b = fmaf(x, g_dv[idx], b);
#pragma unroll
        for (int r = 0; r < R_REL; r++) {
            const float4* pq4 = (const float4*)&g_PQ[r * (IN_F * 8) + idx * 8];
            float4 c0 = pq4[0], c1 = pq4[1];
            const float* c = (const float*)&c0;
            const float* d = (const float*)&c1;
#pragma unroll
            for (int j = 0; j < 4; j++) {
                pr[r * 8 + j]     = fmaf(x, c[j], pr[r * 8 + j]);
                pr[r * 8 + 4 + j] = fmaf(x, d[j], pr[r * 8 + 4 + j]);
            }
        }
    }
#pragma unroll
    for (int off = 16; off; off >>= 1) {
        a += __shfl_xor_sync(0xffffffffu, a, off);
        b += __shfl_xor_sync(0xffffffffu, b, off);
#pragma unroll
        for (int j = 0; j < 24; j++)
            pr[j] += __shfl_xor_sync(0xffffffffu, pr[j], off);
    }
    if (lane == 0) {
        g_sa[node] = a;
        g_sb[node] = b;
#pragma unroll
        for (int r = 0; r < R_REL; r++)
#pragma unroll
            for (int j = 0; j < 8; j++)
                g_pq[((size_t)r * N_NODES + node) * 8 + j] = pr[r * 8 + j] + g_pqc[r * 8 + j];
    }
}

// ---------------- GEMM: C[M,Ncols] = A[M,K] @ B + bias  (f32x2 inner loop) ----------------
// splitB=1: B laid out [R][K][256]; column blocks of 128 never straddle relations.
#define BM 128
#define BN 128
#define BK 16
__global__ __launch_bounds__(256) void k_gemm(const float* __restrict__ A,
                                              const float* __restrict__ B,
                                              const float* __restrict__ bias,
                                              float* __restrict__ C,
                                              int M, int Ncols, int K, int splitB)
{
    __shared__ float As[BK][BM];
    __shared__ float Bs[BK][BN];

    int tid = threadIdx.x;
    int bx = blockIdx.x, by = blockIdx.y;
    int tx = tid & 15, ty = tid >> 4;

    const float* Bp;
    int bn0, ldB;
    if (splitB) {
        int rblk = (bx * BN) / 256;
        Bp = B + (size_t)rblk * K * 256;
        bn0 = bx * BN - rblk * 256;
        ldB = 256;
    } else {
        Bp = B; bn0 = bx * BN; ldB = Ncols;
    }

    int arow0 = by * BM;

    // acc2[p][j]: row-pair (2p, 2p+1) x col j, packed f32x2 (lo=row 2p, hi=row 2p+1)
    uint64_t acc2[4][8];
#pragma unroll
    for (int p = 0; p < 4; p++)
#pragma unroll
        for (int j = 0; j < 8; j++) acc2[p][j] = 0ull;

    for (int kk = 0; kk < K; kk += BK) {
#pragma unroll
        for (int it = 0; it < 2; it++) {
            int lin = tid + it * 256;
            int row = lin >> 2, c4 = lin & 3;
            int gm = arow0 + row;
            float4 v = make_float4(0.f, 0.f, 0.f, 0.f);
            if (gm < M) v = *(const float4*)(A + (size_t)gm * K + kk + c4 * 4);
            As[c4 * 4 + 0][row] = v.x;
            As[c4 * 4 + 1][row] = v.y;
            As[c4 * 4 + 2][row] = v.z;
            As[c4 * 4 + 3][row] = v.w;
        }
#pragma unroll
        for (int it = 0; it < 2; it++) {
            int lin = tid + it * 256;
            int brow = lin >> 5, bc = (lin & 31) * 4;
            float4 v = *(const float4*)(Bp + (size_t)(kk + brow) * ldB + bn0 + bc);
            *(float4*)&Bs[brow][bc] = v;
        }
        __syncthreads();
#pragma unroll
        for (int k = 0; k < BK; k++) {
            // A row-pairs: adjacent floats in the float4 form the f32x2 pair for free
            float4 a0 = *(const float4*)&As[k][ty * 8];
            float4 a1 = *(const float4*)&As[k][ty * 8 + 4];
            uint64_t ap[4];
            ap[0] = pk2(a0.x, a0.y);
            ap[1] = pk2(a0.z, a0.w);
            ap[2] = pk2(a1.x, a1.y);
            ap[3] = pk2(a1.z, a1.w);

            float4 b0 = *(const float4*)&Bs[k][tx * 8];
            float4 b1 = *(const float4*)&Bs[k][tx * 8 + 4];
            float bv[8] = {b0.x, b0.y, b0.z, b0.w, b1.x, b1.y, b1.z, b1.w};
            uint64_t bp[8];
#pragma unroll
            for (int j = 0; j < 8; j++) bp[j] = pk2(bv[j], bv[j]);

#pragma unroll
            for (int p = 0; p < 4; p++)
#pragma unroll
                for (int j = 0; j < 8; j++)
                    ffma2(acc2[p][j], ap[p], bp[j]);
        }
        __syncthreads();
    }

    int col0 = bx * BN + tx * 8;
    float4 bs0 = *(const float4*)&bias[col0];
    float4 bs1 = *(const float4*)&bias[col0 + 4];
    const float* bb = (const float*)&bs0;
    const float* bb2 = (const float*)&bs1;
#pragma unroll
    for (int p = 0; p < 4; p++) {
        float r0[8], r1[8];
#pragma unroll
        for (int j = 0; j < 8; j++) unpk2(r0[j], r1[j], acc2[p][j]);
        int gm0 = arow0 + ty * 8 + 2 * p;
        if (gm0 < M) {
            float4 o0 = make_float4(r0[0] + bb[0], r0[1] + bb[1], r0[2] + bb[2], r0[3] + bb[3]);
            float4 o1 = make_float4(r0[4] + bb2[0], r0[5] + bb2[1], r0[6] + bb2[2], r0[7] + bb2[3]);
            *(float4*)(C + (size_t)gm0 * Ncols + col0)     = o0;
            *(float4*)(C + (size_t)gm0 * Ncols + col0 + 4) = o1;
        }
        int gm1 = gm0 + 1;
        if (gm1 < M) {
            float4 o0 = make_float4(r1[0] + bb[0], r1[1] + bb[1], r1[2] + bb[2], r1[3] + bb[3]);
            float4 o1 = make_float4(r1[4] + bb2[0], r1[5] + bb2[1], r1[6] + bb2[2], r1[7] + bb2[3]);
            *(float4*)(C + (size_t)gm1 * Ncols + col0)     = o0;
            *(float4*)(C + (size_t)gm1 * Ncols + col0 + 4) = o1;
        }
    }
}

// ---------------- CSR build ----------------
__global__ void k_zero()
{
    int i = blockIdx.x * blockDim.x + threadIdx.x;
    if (i < RN) g_cnt[i] = 0;
}

__global__ void k_hist(const int* __restrict__ dst)
{
    int i = blockIdx.x * blockDim.x + threadIdx.x;
    if (i < RE) {
        int r = i / E_EDGES;
        atomicAdd(&g_cnt[r * N_NODES + dst[i]], 1);
    }
}

__global__ __launch_bounds__(1024) void k_scan()
{
    __shared__ int sm[1024];
    int tid = threadIdx.x;
    int carry = 0;
    for (int base = 0; base < RN; base += 1024) {
        int i = base + tid;
        int v = (i < RN) ? g_cnt[i] : 0;
        sm[tid] = v;
        __syncthreads();
#pragma unroll
        for (int off = 1; off < 1024; off <<= 1) {
            int t = (tid >= off) ? sm[tid - off] : 0;
            __syncthreads();
            sm[tid] += t;
            __syncthreads();
        }
        int excl = carry + sm[tid] - v;
        if (i < RN) { g_off[i] = excl; g_cur[i] = excl; }
        carry += sm[1023];
        __syncthreads();
    }
    if (tid == 0) g_off[RN] = carry;
}

__global__ void k_scatter(const int* __restrict__ dst)
{
    int i = blockIdx.x * blockDim.x + threadIdx.x;
    if (i < RE) {
        int r = i / E_EDGES;
        int pos = atomicAdd(&g_cur[r * N_NODES + dst[i]], 1);
        g_elist[pos] = i - r * E_EDGES;
    }
}

// ---------------- aggregation: warp per (relation, node), online softmax ----------------
__global__ __launch_bounds__(256) void k_agg(const int* __restrict__ src)
{
    int widx = (blockIdx.x * blockDim.x + threadIdx.x) >> 5;
    int lane = threadIdx.x & 31;
    if (widx >= RN) return;
    int r = widx / N_NODES;
    int n = widx - r * N_NODES;
    int start = g_off[widx], end = g_off[widx + 1];
    size_t obase = (size_t)n * RH + r * H_DIM;

    if (start == end) {
#pragma unroll
        for (int k = 0; k < 8; k++) g_agg[obase + lane + 32 * k] = 0.f;
        return;
    }

    float qv[4];
    {
        const float* qp = &g_pq[((size_t)r * N_NODES + n) * 8 + 4];
#pragma unroll
        for (int hh = 0; hh < 4; hh++) qv[hh] = qp[hh];
    }
    float b_n = g_sb[n];
    float cs = g_Cs;
    const float* hwbase = g_hw + r * H_DIM;
    const int* srcR = src + (size_t)r * E_EDGES;
    const float* pqR = g_pq + (size_t)r * N_NODES * 8;

    float m[4], den[4], acc[8];
#pragma unroll
    for (int hh = 0; hh < 4; hh++) { m[hh] = -1e30f; den[hh] = 0.f; }
#pragma unroll
    for (int k = 0; k < 8; k++) acc[k] = 0.f;

    for (int pos = start; pos < end; pos++) {
        int e = g_elist[pos];
        int s = srcR[e];
        float sc = g_sa[s] + b_n + cs;
        float sgn = (float)((sc > 0.f) - (sc < 0.f));
        float4 pv = *(const float4*)&pqR[(size_t)s * 8];
        float pvv[4] = {pv.x, pv.y, pv.z, pv.w};
        float f[4], w[4];
#pragma unroll
        for (int hh = 0; hh < 4; hh++) {
            float al = fmaf(sgn, pvv[hh], qv[hh]);
            al = (al > 0.f) ? al : 0.01f * al;
            float nm = fmaxf(m[hh], al);
            f[hh] = __expf(m[hh] - nm);
            float wv = __expf(al - nm);
            den[hh] = den[hh] * f[hh] + wv;
            m[hh] = nm;
            w[hh] = wv * sgn;
        }
        const float* row = hwbase + (size_t)s * RH;
#pragma unroll
        for (int k = 0; k < 8; k++)
            acc[k] = acc[k] * f[k >> 1] + w[k >> 1] * row[lane + 32 * k];
    }
    float inv[4];
#pragma unroll
    for (int hh = 0; hh < 4; hh++) inv[hh] = 1.f / den[hh];
#pragma unroll
    for (int k = 0; k < 8; k++)
        g_agg[obase + lane + 32 * k] = acc[k] * inv[k >> 1];
}

// ---------------- launch ----------------
extern "C" void kernel_launch(void* const* d_in, const int* in_sizes, int n_in,
                              void* d_out, int out_size)
{
    const float* h    = (const float*)d_in[0];
    const float* dW   = (const float*)d_in[1];
    const float* db   = (const float*)d_in[2];
    const float* fW   = (const float*)d_in[3];
    const float* fb   = (const float*)d_in[4];
    const float* wW   = (const float*)d_in[5];
    const float* wb   = (const float*)d_in[6];
    const float* aW   = (const float*)d_in[7];
    const float* ab   = (const float*)d_in[8];
    const float* linW = (const float*)d_in[9];
    const float* linb = (const float*)d_in[10];
    const int*   src  = (const int*)d_in[11];
    const int*   dst  = (const int*)d_in[12];
    float* out = (float*)d_out;

    float *p_hw = nullptr, *p_agg = nullptr;
    cudaGetSymbolAddress((void**)&p_hw, g_hw);
    cudaGetSymbolAddress((void**)&p_agg, g_agg);

    k_precompute<<<1, 128>>>(dW, db, fW, fb, wW, wb, aW, ab);          // 1
    k_zero<<<(RN + 255) / 256, 256>>>();                               // 2
    k_node_scalars<<<N_NODES / 4, 128>>>(h);                           // 3
    k_gemm<<<dim3(RH / BN, (N_NODES + BM - 1) / BM), 256>>>(h, wW, wb, p_hw,
                                                            N_NODES, RH, IN_F, 1); // 4
    k_hist<<<(RE + 255) / 256, 256>>>(dst);                            // 5
    k_scan<<<1, 1024>>>();                                             // 6
    k_scatter<<<(RE + 255) / 256, 256>>>(dst);                         // 7
    k_agg<<<RN / 8, 256>>>(src);                                       // 8
    k_gemm<<<dim3(H_DIM / BN, (N_NODES + BM - 1) / BM), 256>>>(p_agg, linW, linb, out,
                                                               N_NODES, H_DIM, RH, 0); // 9
}